// round 17
// baseline (speedup 1.0000x reference)
#include <cuda_runtime.h>
#include <cuda_fp16.h>
#include <mma.h>
#include <cstdint>

using namespace nvcuda;

#define BB 1024
#define CC 1000
#define HH 512
#define NEG_INF (__int_as_float(0xff800000))

// ---------------- scratch (__device__ globals; zero-initialized) ----------------
__device__ float g_GA[1024 * 1024];           // split-K Gram partial (K 0..255)
__device__ float g_GB[1024 * 1024];           // split-K Gram partial (K 256..511)
__device__ float g_normA[1024];               // diagonal partials (consistent norms)
__device__ float g_normB[1024];

// ---------------------------------------------------------------------------
// k_gram: fused convert+Gram (identical to the 14.8us R15 kernel).
// 272 CTAs = 136 upper-tri 64x64 tile-pairs x 2 K-halves, 256 thr.
// ---------------------------------------------------------------------------
#define NTT 16
#define NPAIR (NTT * (NTT + 1) / 2)   // 136
#define NGRAM (2 * NPAIR)             // 272
#define KHALF (HH / 2)                // 256
#define SST2 264                      // fp16 smem stride: 33r%32 distinct
#define OPHALF (64 * SST2)
#define SMEMSZ (2 * OPHALF * 2)       // 67584 B dynamic smem

extern __shared__ char dsm[];

__global__ void __launch_bounds__(256, 2)
k_gram(const float* __restrict__ w) {
    __half* sA = (__half*)dsm;
    __half* sB = sA + OPHALF;
    float* Cs = (float*)dsm;          // epilogue overlay: 64x68 f32

    const int t = threadIdx.x;
    const int wid = t >> 5;
    const int wr = (wid >> 1) * 16;   // 0..48
    const int wc = (wid & 1) * 32;    // 0,32

    const int kh = blockIdx.x & 1;
    int p = blockIdx.x >> 1, ti = 0;
    while (p >= NTT - ti) { p -= NTT - ti; ti++; }
    const int tj = ti + p;
    const int k0 = kh * KHALF;

    // Phase 1: load f32 tiles, convert, store fp16 to smem (once, full K-half)
    #pragma unroll
    for (int i = 0; i < 16; i++) {
        const int idx = i * 256 + t;          // < 4096
        const int fr = idx >> 6;
        const int fc = (idx & 63) * 4;
        const int ra = min(ti * 64 + fr, CC - 1);
        const int rb = min(tj * 64 + fr, CC - 1);
        const float4 va = __ldg((const float4*)(w + (long)ra * HH + k0 + fc));
        const float4 vb = __ldg((const float4*)(w + (long)rb * HH + k0 + fc));
        uint32_t a0, a1, b0, b1;
        asm("cvt.rn.f16x2.f32 %0, %1, %2;" : "=r"(a0) : "f"(va.y), "f"(va.x));
        asm("cvt.rn.f16x2.f32 %0, %1, %2;" : "=r"(a1) : "f"(va.w), "f"(va.z));
        asm("cvt.rn.f16x2.f32 %0, %1, %2;" : "=r"(b0) : "f"(vb.y), "f"(vb.x));
        asm("cvt.rn.f16x2.f32 %0, %1, %2;" : "=r"(b1) : "f"(vb.w), "f"(vb.z));
        *(uint2*)&sA[fr * SST2 + fc] = make_uint2(a0, a1);
        *(uint2*)&sB[fr * SST2 + fc] = make_uint2(b0, b1);
    }
    __syncthreads();

    // Phase 2: MMA sweep, K=256 in 16 steps, no syncs
    wmma::fragment<wmma::accumulator, 16, 16, 16, float> acc[2];
    wmma::fill_fragment(acc[0], 0.f);
    wmma::fill_fragment(acc[1], 0.f);

    #pragma unroll
    for (int kk = 0; kk < KHALF; kk += 16) {
        wmma::fragment<wmma::matrix_a, 16, 16, 16, __half, wmma::row_major> af;
        wmma::fragment<wmma::matrix_b, 16, 16, 16, __half, wmma::col_major> bf[2];
        wmma::load_matrix_sync(af, sA + wr * SST2 + kk, SST2);
        wmma::load_matrix_sync(bf[0], sB + wc * SST2 + kk, SST2);
        wmma::load_matrix_sync(bf[1], sB + (wc + 16) * SST2 + kk, SST2);
        wmma::mma_sync(acc[0], af, bf[0], acc[0]);
        wmma::mma_sync(acc[1], af, bf[1], acc[1]);
    }

    // Epilogue: smem round-trip, coalesced upper + mirror stores
    __syncthreads();
    #pragma unroll
    for (int j = 0; j < 2; j++)
        wmma::store_matrix_sync(Cs + wr * 68 + wc + 16 * j, acc[j], 68,
                                wmma::mem_row_major);
    __syncthreads();

    float* G = kh ? g_GB : g_GA;
    for (int idx = t; idx < 64 * 16; idx += 256) {       // upper tile
        const int r = idx >> 4, c4 = idx & 15;
        const float4 v = *(const float4*)(Cs + r * 68 + c4 * 4);
        *(float4*)&G[(long)(ti * 64 + r) * 1024 + tj * 64 + c4 * 4] = v;
    }
    for (int idx = t; idx < 64 * 16; idx += 256) {       // mirror (transposed)
        const int c = idx >> 4, r4 = idx & 15;
        float4 v;
        v.x = Cs[(4 * r4 + 0) * 68 + c];
        v.y = Cs[(4 * r4 + 1) * 68 + c];
        v.z = Cs[(4 * r4 + 2) * 68 + c];
        v.w = Cs[(4 * r4 + 3) * 68 + c];
        *(float4*)&G[(long)(tj * 64 + c) * 1024 + ti * 64 + 4 * r4] = v;
    }
    if (ti == tj && t < 64)            // consistent norms from diagonal
        (kh ? g_normB : g_normA)[ti * 64 + t] = Cs[t * 68 + t];
}

// ---------------------------------------------------------------------------
// k_bot: 4 rows per block (256 blocks x 256 thr). Batched y loads, fused
// copy + argmax (one sync for all 4 rows) + y_bot (one sync).
// ---------------------------------------------------------------------------
#define RPB 4

__global__ void __launch_bounds__(256)
k_bot(const float* __restrict__ y,
      const float* __restrict__ eps_p,
      const float* __restrict__ lip_p,
      float* __restrict__ out) {
    const int t = threadIdx.x;
    const int lane = t & 31, wid = t >> 5;
    const int b0 = blockIdx.x * RPB;
    __shared__ float sv[RPB][8];
    __shared__ int   si[RPB][8];
    __shared__ float symax[RPB];
    __shared__ int   sj[RPB];

    const bool yok = (t < CC / 4);

    // ---- batched y loads for all 4 rows ----
    float4 vy[RPB];
    #pragma unroll
    for (int r = 0; r < RPB; r++)
        if (yok) vy[r] = __ldg((const float4*)(y + (long)(b0 + r) * CC) + t);

    // ---- copy + per-row local argmax ----
    float vmax[RPB]; int imax[RPB];
    #pragma unroll
    for (int r = 0; r < RPB; r++) {
        vmax[r] = NEG_INF; imax[r] = 0x7fffffff;
        if (yok) {
            float* orow = out + (long)(b0 + r) * (CC + 1);
            const int c = t * 4;
            orow[c] = vy[r].x; orow[c + 1] = vy[r].y;
            orow[c + 2] = vy[r].z; orow[c + 3] = vy[r].w;
            vmax[r] = vy[r].x; imax[r] = c;
            if (vy[r].y > vmax[r]) { vmax[r] = vy[r].y; imax[r] = c + 1; }
            if (vy[r].z > vmax[r]) { vmax[r] = vy[r].z; imax[r] = c + 2; }
            if (vy[r].w > vmax[r]) { vmax[r] = vy[r].w; imax[r] = c + 3; }
        }
    }
    #pragma unroll
    for (int r = 0; r < RPB; r++) {
        #pragma unroll
        for (int o = 16; o > 0; o >>= 1) {
            const float v2 = __shfl_xor_sync(0xffffffffu, vmax[r], o);
            const int   i2 = __shfl_xor_sync(0xffffffffu, imax[r], o);
            if (v2 > vmax[r] || (v2 == vmax[r] && i2 < imax[r])) {
                vmax[r] = v2; imax[r] = i2;
            }
        }
        if (lane == 0) { sv[r][wid] = vmax[r]; si[r][wid] = imax[r]; }
    }
    __syncthreads();
    if (t < RPB) {                     // thread t finalizes row t
        float bv = sv[t][0]; int bi = si[t][0];
        #pragma unroll
        for (int k = 1; k < 8; k++)
            if (sv[t][k] > bv || (sv[t][k] == bv && si[t][k] < bi)) {
                bv = sv[t][k]; bi = si[t][k];
            }
        symax[t] = bv; sj[t] = bi;
    }
    __syncthreads();

    // ---- y_bot: batched G loads for all rows, pruned sqrt ----
    const float s  = (*eps_p) * fabsf(*lip_p);
    const float s2 = s * s;

    float4 na, nb;
    float4 ga[RPB], gb[RPB];
    int j[RPB]; float ymax[RPB], nj[RPB];
    if (yok) {
        na = *((const float4*)g_normA + t);
        nb = *((const float4*)g_normB + t);
    }
    #pragma unroll
    for (int r = 0; r < RPB; r++) {
        j[r] = sj[r]; ymax[r] = symax[r];
        nj[r] = g_normA[j[r]] + g_normB[j[r]];
        if (yok) {
            ga[r] = *((const float4*)(g_GA + (long)j[r] * 1024) + t);
            gb[r] = *((const float4*)(g_GB + (long)j[r] * 1024) + t);
        }
    }

    float best[RPB];
    #pragma unroll
    for (int r = 0; r < RPB; r++) {
        best[r] = NEG_INF;
        if (yok) {
            const float ye[4] = {vy[r].x, vy[r].y, vy[r].z, vy[r].w};
            const float ge[4] = {ga[r].x + gb[r].x, ga[r].y + gb[r].y,
                                 ga[r].z + gb[r].z, ga[r].w + gb[r].w};
            const float ne[4] = {na.x + nb.x, na.y + nb.y, na.z + nb.z, na.w + nb.w};
            #pragma unroll
            for (int e = 0; e < 4; e++) {
                if (ye[e] == ymax[r]) continue;   // ref masks y==ymax -> -inf
                float sq = fmaf(-2.f, ge[e], nj[r] + ne[e]);
                if (sq < 0.f) sq = 0.f;
                const float d = best[r] - ye[e];
                if (d <= 0.f || sq * s2 > d * d)
                    best[r] = fmaxf(best[r], fmaf(s, sqrtf(sq), ye[e]));
            }
        }
        #pragma unroll
        for (int o = 16; o > 0; o >>= 1)
            best[r] = fmaxf(best[r], __shfl_xor_sync(0xffffffffu, best[r], o));
        if (lane == 0) sv[r][wid] = best[r];
    }
    __syncthreads();
    if (t < RPB) {
        float rr = sv[t][0];
        #pragma unroll
        for (int k = 1; k < 8; k++) rr = fmaxf(rr, sv[t][k]);
        out[(long)(b0 + t) * (CC + 1) + CC] = rr;
    }
}

// ---------------------------------------------------------------------------
extern "C" void kernel_launch(void* const* d_in, const int* in_sizes, int n_in,
                              void* d_out, int out_size) {
    const float* y   = (const float*)d_in[0];
    const float* w   = (const float*)d_in[1];
    const float* eps = (const float*)d_in[2];
    const float* lip = (const float*)d_in[3];
    float* out = (float*)d_out;

    static bool attr = false;
    if (!attr) {
        cudaFuncSetAttribute(k_gram, cudaFuncAttributeMaxDynamicSharedMemorySize,
                             SMEMSZ);
        attr = true;
    }

    k_gram<<<NGRAM, 256, SMEMSZ>>>(w);
    k_bot<<<BB / RPB, 256>>>(y, eps, lip, out);
}